// round 12
// baseline (speedup 1.0000x reference)
#include <cuda_runtime.h>
#include <math.h>

// Problem constants
#define BB   64
#define SS   512
#define DD   128
#define DH   64
#define RTOT (BB*SS)                    // 32768 rows

static constexpr size_t SZ       = (size_t)RTOT * DD;      // 4194304 floats
static constexpr size_t OFF_T    = 0;                      // t,v,a at 0,1,2
static constexpr size_t OFF_QKV  = 3*SZ;                   // 18 buffers (unit*3 + {q,k,v})
static constexpr size_t OFF_CTX  = 21*SZ;                  // 6 buffers
static constexpr size_t OFF_OUT3 = 27*SZ;                  // ot, ov, oa
static constexpr size_t OFF_VSUM = 30*SZ;                  // [6][64][2][64]
static constexpr size_t OFF_GX   = OFF_VSUM + 49152;
static constexpr size_t GX_PER   = (size_t)RTOT * 384;     // 12582912
static constexpr size_t OFF_WIHT = OFF_GX + 6*GX_PER;      // 6 x [128][384]
static constexpr size_t OFF_WHHT = OFF_WIHT + 6*49152;
static constexpr size_t OFF_HSUM = OFF_WHHT + 6*49152;     // [6][64][128]
static constexpr size_t OFF_OM   = OFF_HSUM + 49152;       // [64][384]
static constexpr size_t SCRATCH_TOTAL = OFF_OM + 24576;

__device__ float g_scratch[SCRATCH_TOTAL];

// ---------------- packed fp32x2 FMA (FFMA2; ptxas never auto-generates) -------
__device__ __forceinline__ void ffma2(float2& d, float2 a, float2 b) {
    asm("fma.rn.f32x2 %0, %1, %2, %0;"
        : "+l"(reinterpret_cast<unsigned long long&>(d))
        : "l"(reinterpret_cast<unsigned long long&>(a)),
          "l"(reinterpret_cast<unsigned long long&>(b)));
}
__device__ __forceinline__ float2 dup2(float a) { return make_float2(a, a); }

// ---------------- shared GEMM core: 128x128 tile, BK=16, 256 thr, 8x8 micro ---
// acc[r][c] is float2 covering output cols tx*8 + 2c, +1.
__device__ __forceinline__ void gemm_core(
    const float* __restrict__ Arow,   // A + rowbase*K (row stride == K)
    int K,
    const float* __restrict__ Wp,     // W + nbase     (row stride == ldw)
    int ldw,
    float2 (&acc)[8][4],
    float* As, float* Ws, int tid)
{
    int tx = tid & 15, ty = tid >> 4;
    for (int k0 = 0; k0 < K; k0 += 16) {
#pragma unroll
        for (int p = 0; p < 8; p++) {
            int idx = tid + p*256;
            int r = idx >> 4, kk = idx & 15;
            int k = k0 + kk;
            As[r*17 + kk] = (k < K) ? Arow[(size_t)r*K + k] : 0.f;
        }
#pragma unroll
        for (int p = 0; p < 8; p++) {
            int idx = tid + p*256;
            int kk = idx >> 7, n = idx & 127;
            int k = k0 + kk;
            Ws[kk*128 + n] = (k < K) ? Wp[(size_t)k*ldw + n] : 0.f;
        }
        __syncthreads();
#pragma unroll
        for (int kk = 0; kk < 16; kk++) {
            float4 w0 = *(const float4*)&Ws[kk*128 + tx*8];
            float4 w1 = *(const float4*)&Ws[kk*128 + tx*8 + 4];
            float2 wv0 = make_float2(w0.x, w0.y);
            float2 wv1 = make_float2(w0.z, w0.w);
            float2 wv2 = make_float2(w1.x, w1.y);
            float2 wv3 = make_float2(w1.z, w1.w);
#pragma unroll
            for (int r = 0; r < 8; r++) {
                float2 aa = dup2(As[(ty*8 + r)*17 + kk]);
                ffma2(acc[r][0], aa, wv0);
                ffma2(acc[r][1], aa, wv1);
                ffma2(acc[r][2], aa, wv2);
                ffma2(acc[r][3], aa, wv3);
            }
        }
        __syncthreads();
    }
}

__device__ __forceinline__ void epi_plain(
    float2 (&acc)[8][4], const float* __restrict__ bias,
    float* __restrict__ C, int ldc, int rowbase, int nbase, int tid)
{
    int tx = tid & 15, ty = tid >> 4;
    float4 b0 = *(const float4*)&bias[nbase + tx*8];
    float4 b1 = *(const float4*)&bias[nbase + tx*8 + 4];
#pragma unroll
    for (int r = 0; r < 8; r++) {
        int row = rowbase + ty*8 + r;
        float* Cp = C + (size_t)row*ldc + nbase + tx*8;
        float4 o0 = make_float4(acc[r][0].x + b0.x, acc[r][0].y + b0.y,
                                acc[r][1].x + b0.z, acc[r][1].y + b0.w);
        float4 o1 = make_float4(acc[r][2].x + b1.x, acc[r][2].y + b1.y,
                                acc[r][3].x + b1.z, acc[r][3].y + b1.w);
        *(float4*)Cp       = o0;
        *(float4*)(Cp + 4) = o1;
    }
}

// ---------------- input projection GEMMs ----------------
__global__ __launch_bounds__(256, 2)
void proj_gemm(const float* __restrict__ A, const float* __restrict__ W,
               const float* __restrict__ bias, int K, int dst)
{
    __shared__ float As[128*17];
    __shared__ float Ws[16*128];
    int tid = threadIdx.x;
    int rowbase = blockIdx.x * 128;
    float2 acc[8][4];
#pragma unroll
    for (int r = 0; r < 8; r++)
#pragma unroll
        for (int c = 0; c < 4; c++) acc[r][c] = make_float2(0.f, 0.f);
    gemm_core(A + (size_t)rowbase*K, K, W, 128, acc, As, Ws, tid);
    epi_plain(acc, bias, g_scratch + OFF_T + (size_t)dst*SZ, 128, rowbase, 0, tid);
}

// ---------------- batched QKV GEMMs (z = unit*3 + which) ----------------
__global__ __launch_bounds__(256, 2)
void qkv_gemm(const float* __restrict__ Wq, const float* __restrict__ Wk,
              const float* __restrict__ Wv, const float* __restrict__ bq,
              const float* __restrict__ bk, const float* __restrict__ bv)
{
    __shared__ float As[128*17];
    __shared__ float Ws[16*128];
    const int qsel[6] = {0,2,0,1,1,2};
    const int ksel[6] = {2,0,1,0,2,1};
    int tid = threadIdx.x;
    int z = blockIdx.z;
    int unit = z / 3, which = z % 3;
    int src = (which == 0) ? qsel[unit] : ksel[unit];
    const float* A = g_scratch + OFF_T + (size_t)src*SZ;
    const float* W = ((which == 0) ? Wq : (which == 1) ? Wk : Wv) + (size_t)unit*16384;
    const float* b = ((which == 0) ? bq : (which == 1) ? bk : bv) + unit*128;
    float* C = g_scratch + OFF_QKV + (size_t)z*SZ;
    int rowbase = blockIdx.x * 128;
    float2 acc[8][4];
#pragma unroll
    for (int r = 0; r < 8; r++)
#pragma unroll
        for (int c = 0; c < 4; c++) acc[r][c] = make_float2(0.f, 0.f);
    gemm_core(A + (size_t)rowbase*128, 128, W, 128, acc, As, Ws, tid);
    epi_plain(acc, b, C, 128, rowbase, 0, tid);
}

// ---------------- V column sums (for ctx = Vsum - softmax@V) ----------------
__global__ void vsum_kernel()
{
    int b = blockIdx.x, h = blockIdx.y, u = blockIdx.z, d = threadIdx.x;
    const float* V = g_scratch + OFF_QKV + (size_t)(u*3 + 2)*SZ
                   + (size_t)b*SS*DD + h*DH + d;
    float s = 0.f;
#pragma unroll 8
    for (int k = 0; k < SS; k++) s += V[(size_t)k*DD];
    g_scratch[OFF_VSUM + (((size_t)u*64 + b)*2 + h)*64 + d] = s;
}

// ---------------- batched flash attention ----------------
// grid = (8 q-tiles, B*H=128, 6 units), block = 256, dyn smem = 4*64*68*4 B.
// ctx = Vsum - softmax(QK^T/8)@V  (exactly (1 - softmax)@V).
#define ATTN_SMEM (4*64*68*4)

__global__ __launch_bounds__(256, 2)
void attn_flash()
{
    extern __shared__ float sm[];
    float* Qs = sm;              // [64][68]  (row-major, q rows)
    float* Ks = sm + 64*68;      // [64][68]  TRANSPOSED: Ks[d][k]
    float* Vs = sm + 2*64*68;    // [64][68]  (row = k)
    float* Ps = sm + 3*64*68;    // [64][68]  (row = q, col = k)

    int tid = threadIdx.x;
    int u = blockIdx.z;
    int bh = blockIdx.y;
    int b = bh >> 1, h = bh & 1;
    int q0 = blockIdx.x * 64;

    const float* Qb = g_scratch + OFF_QKV + (size_t)(u*3 + 0)*SZ;
    const float* Kb = g_scratch + OFF_QKV + (size_t)(u*3 + 1)*SZ;
    const float* Vb = g_scratch + OFF_QKV + (size_t)(u*3 + 2)*SZ;
    size_t baseQ  = ((size_t)b*SS + q0)*DD + h*DH;
    size_t baseKV = ((size_t)b*SS)*DD + h*DH;

#pragma unroll
    for (int p = 0; p < 16; p++) {
        int idx = tid + p*256;
        int r = idx >> 6, c = idx & 63;
        Qs[r*68 + c] = Qb[baseQ + (size_t)r*DD + c];
    }

    int tx = tid & 15;   // 4 output d-cols / 4 k-cols
    int ty = tid >> 4;   // 4 q rows

    float2 oacc[4][2];
    float m[4], l[4];
#pragma unroll
    for (int i = 0; i < 4; i++) {
        oacc[i][0] = make_float2(0.f, 0.f);
        oacc[i][1] = make_float2(0.f, 0.f);
        m[i] = -1e30f; l[i] = 0.f;
    }

    for (int kt = 0; kt < 8; kt++) {
        __syncthreads();                       // prev PV done with Vs/Ps
#pragma unroll
        for (int p = 0; p < 16; p++) {
            int idx = tid + p*256;
            int r = idx >> 6, c = idx & 63;
            size_t g = baseKV + (size_t)(kt*64 + r)*DD + c;
            Ks[c*68 + r] = Kb[g];              // transposed store
            Vs[r*68 + c] = Vb[g];
        }
        __syncthreads();

        // scores: s2[i][0]=(j0,j1), s2[i][1]=(j2,j3)
        float2 s2[4][2];
#pragma unroll
        for (int i = 0; i < 4; i++) { s2[i][0] = make_float2(0.f,0.f); s2[i][1] = make_float2(0.f,0.f); }
#pragma unroll 8
        for (int d = 0; d < 64; d++) {
            float4 k4 = *(const float4*)&Ks[d*68 + tx*4];
            float2 ka = make_float2(k4.x, k4.y);
            float2 kb2 = make_float2(k4.z, k4.w);
#pragma unroll
            for (int i = 0; i < 4; i++) {
                float2 qq = dup2(Qs[(ty*4 + i)*68 + d]);
                ffma2(s2[i][0], qq, ka);
                ffma2(s2[i][1], qq, kb2);
            }
        }

        // online softmax update + stash P
#pragma unroll
        for (int i = 0; i < 4; i++) {
            float s0 = s2[i][0].x * 0.125f;
            float s1 = s2[i][0].y * 0.125f;
            float s2v = s2[i][1].x * 0.125f;
            float s3 = s2[i][1].y * 0.125f;
            float tm = fmaxf(fmaxf(s0, s1), fmaxf(s2v, s3));
#pragma unroll
            for (int off = 8; off >= 1; off >>= 1)
                tm = fmaxf(tm, __shfl_xor_sync(0xffffffffu, tm, off));
            float mn = fmaxf(m[i], tm);
            float corr = __expf(m[i] - mn);
            float p0 = __expf(s0 - mn);
            float p1 = __expf(s1 - mn);
            float p2 = __expf(s2v - mn);
            float p3 = __expf(s3 - mn);
            float ps = p0 + p1 + p2 + p3;
#pragma unroll
            for (int off = 8; off >= 1; off >>= 1)
                ps += __shfl_xor_sync(0xffffffffu, ps, off);
            l[i] = l[i]*corr + ps;
            oacc[i][0].x *= corr; oacc[i][0].y *= corr;
            oacc[i][1].x *= corr; oacc[i][1].y *= corr;
            m[i] = mn;
            *(float4*)&Ps[(ty*4 + i)*68 + tx*4] = make_float4(p0, p1, p2, p3);
        }
        __syncthreads();                       // Ps visible

        // PV: oacc[i] += P[row i] @ Vtile
#pragma unroll 4
        for (int k4i = 0; k4i < 16; k4i++) {
            float4 p4[4];
#pragma unroll
            for (int i = 0; i < 4; i++)
                p4[i] = *(const float4*)&Ps[(ty*4 + i)*68 + k4i*4];
#pragma unroll
            for (int kk = 0; kk < 4; kk++) {
                float4 v4 = *(const float4*)&Vs[(k4i*4 + kk)*68 + tx*4];
                float2 va = make_float2(v4.x, v4.y);
                float2 vb2 = make_float2(v4.z, v4.w);
#pragma unroll
                for (int i = 0; i < 4; i++) {
                    float pk = (kk == 0) ? p4[i].x : (kk == 1) ? p4[i].y
                             : (kk == 2) ? p4[i].z : p4[i].w;
                    float2 pp = dup2(pk);
                    ffma2(oacc[i][0], pp, va);
                    ffma2(oacc[i][1], pp, vb2);
                }
            }
        }
    }

    float4 vs4 = *(const float4*)&g_scratch[OFF_VSUM + (((size_t)u*64 + b)*2 + h)*64 + tx*4];
    float* Cb = g_scratch + OFF_CTX + (size_t)u*SZ;
#pragma unroll
    for (int i = 0; i < 4; i++) {
        float inv = 1.f / l[i];
        size_t idx = ((size_t)b*SS + q0 + ty*4 + i)*DD + h*DH + tx*4;
        float4 o;
        o.x = vs4.x - oacc[i][0].x * inv;
        o.y = vs4.y - oacc[i][0].y * inv;
        o.z = vs4.z - oacc[i][1].x * inv;
        o.w = vs4.w - oacc[i][1].y * inv;
        *(float4*)&Cb[idx] = o;
    }
}

// ---------------- batched out-proj + LayerNorm + 0.5*accumulate --------------
// phase 0: units 0,1,2 (beta=0); phase 1: units 3,4,5 (beta=1)
__global__ __launch_bounds__(256, 2)
void epi_gemm(const float* __restrict__ Wd, const float* __restrict__ bd,
              const float* __restrict__ lng, const float* __restrict__ lnb,
              int phase)
{
    __shared__ float As[128*17];
    __shared__ float Ws[16*128];
    const int accsel[6] = {2,0,1,0,2,1};   // -> {ot,ov,oa} index
    int tid = threadIdx.x;
    int unit = phase*3 + blockIdx.z;
    const float* A = g_scratch + OFF_CTX + (size_t)unit*SZ;
    float* C = g_scratch + OFF_OUT3 + (size_t)accsel[unit]*SZ;
    const float* bias = bd + unit*128;
    const float* lg = lng + unit*128;
    const float* lb = lnb + unit*128;
    int rowbase = blockIdx.x * 128;

    float2 acc[8][4];
#pragma unroll
    for (int r = 0; r < 8; r++)
#pragma unroll
        for (int c = 0; c < 4; c++) acc[r][c] = make_float2(0.f, 0.f);
    gemm_core(A + (size_t)rowbase*128, 128, Wd + (size_t)unit*16384, 128, acc, As, Ws, tid);

    int tx = tid & 15, ty = tid >> 4;
    const float inv = 1.0f / 128.0f;
#pragma unroll
    for (int r = 0; r < 8; r++) {
        float vals[8];
        float s = 0.f, s2 = 0.f;
#pragma unroll
        for (int c = 0; c < 8; c++) {
            float2 a2 = acc[r][c >> 1];
            float vv = ((c & 1) ? a2.y : a2.x) + bias[tx*8 + c];
            vals[c] = vv; s += vv; s2 += vv*vv;
        }
#pragma unroll
        for (int off = 8; off >= 1; off >>= 1) {
            s  += __shfl_xor_sync(0xffffffffu, s,  off);
            s2 += __shfl_xor_sync(0xffffffffu, s2, off);
        }
        float mean = s * inv;
        float var  = s2 * inv - mean*mean;
        float rstd = rsqrtf(var + 1e-5f);
        int row = rowbase + ty*8 + r;
#pragma unroll
        for (int c = 0; c < 8; c++) {
            int col = tx*8 + c;
            float o = (vals[c] - mean) * rstd * lg[col] + lb[col];
            size_t idx = (size_t)row*128 + col;
            if (phase == 0) C[idx] = 0.5f * o;
            else            C[idx] = C[idx] + 0.5f * o;
        }
    }
}

// ---------------- batched GRU input-gate GEMMs (z = dir6) ----------------
__global__ __launch_bounds__(256, 2)
void gx_gemm(const float* __restrict__ gbih)
{
    __shared__ float As[128*17];
    __shared__ float Ws[16*128];
    int tid = threadIdx.x;
    int z = blockIdx.z;                         // dir6
    const float* A = g_scratch + OFF_OUT3 + (size_t)(z >> 1)*SZ;
    const float* Wp = g_scratch + OFF_WIHT + (size_t)z*49152;
    float* C = g_scratch + OFF_GX + (size_t)z*GX_PER;
    int rowbase = blockIdx.x * 128;
    int nbase   = blockIdx.y * 128;

    float2 acc[8][4];
#pragma unroll
    for (int r = 0; r < 8; r++)
#pragma unroll
        for (int c = 0; c < 4; c++) acc[r][c] = make_float2(0.f, 0.f);
    gemm_core(A + (size_t)rowbase*128, 128, Wp + nbase, 384, acc, As, Ws, tid);
    epi_plain(acc, gbih + z*384, C, 384, rowbase, nbase, tid);
}

// ---------------- GRU weight transposes ----------------
__global__ void transpose_w_kernel(const float* __restrict__ gWih,
                                   const float* __restrict__ gWhh)
{
    int mIdx = blockIdx.x;                 // 0..11
    const float* src = (mIdx < 6 ? gWih : gWhh) + (size_t)(mIdx % 6)*384*128;
    float* dst = g_scratch + (mIdx < 6 ? OFF_WIHT : OFF_WHHT) + (size_t)(mIdx % 6)*49152;
    for (int idx = threadIdx.x; idx < 128*384; idx += blockDim.x) {
        int k = idx / 384, n = idx % 384;
        dst[idx] = src[(size_t)n*128 + k];
    }
}

// ---------------- GRU recurrence (384 chains) ----------------
__global__ __launch_bounds__(384)
void gru_kernel(const float* __restrict__ gbhh)
{
    int dir6 = blockIdx.x >> 6;
    int b    = blockIdx.x & 63;
    int j    = threadIdx.x;

    const float* wp = g_scratch + OFF_WHHT + (size_t)dir6*49152 + j;
    float2 w2[64];
#pragma unroll
    for (int k = 0; k < 64; k++)
        w2[k] = make_float2(wp[(size_t)(2*k)*384], wp[(size_t)(2*k + 1)*384]);
    float bh = gbhh[dir6*384 + j];

    __shared__ float h[128];
    __shared__ float gh[384];
    __shared__ float gxs[384];
    __shared__ float hs[128];
    if (j < 128) { h[j] = 0.f; hs[j] = 0.f; }

    const float* gxb = g_scratch + OFF_GX + (size_t)dir6*GX_PER + (size_t)b*SS*384;
    int rev = dir6 & 1;
    const float2* h2 = (const float2*)h;

    for (int step = 0; step < SS; step++) {
        int t = rev ? (SS - 1 - step) : step;
        float gxv = gxb[(size_t)t*384 + j];     // prefetch (latency hidden by matvec)
        __syncthreads();                        // h ready; prev gxs reads done
        gxs[j] = gxv;
        float2 acc = make_float2(0.f, 0.f);
#pragma unroll
        for (int k = 0; k < 64; k++) ffma2(acc, w2[k], h2[k]);
        gh[j] = acc.x + acc.y + bh;
        __syncthreads();                        // gh + gxs complete
        if (j < 128) {
            float r  = 1.f / (1.f + __expf(-(gxs[j]       + gh[j])));
            float z  = 1.f / (1.f + __expf(-(gxs[128 + j] + gh[128 + j])));
            float n  = tanhf(gxs[256 + j] + r * gh[256 + j]);
            float hn = (1.f - z)*n + z*h[j];
            h[j]  = hn;
            hs[j] += hn;
        }
    }
    __syncthreads();
    if (j < 128) g_scratch[OFF_HSUM + ((size_t)dir6*64 + b)*128 + j] = hs[j];
}

// ---------------- combine h-sums -> pooled features [64,384] ----------------
__global__ void combine_kernel()
{
    int b = blockIdx.x;
    int j = threadIdx.x;          // 0..383
    int seg = j >> 7, i = j & 127;
    float v = g_scratch[OFF_HSUM + ((size_t)seg*64 + b)*128 + i]
            + g_scratch[OFF_HSUM + ((size_t)(seg + 3)*64 + b)*128 + i];
    g_scratch[OFF_OM + (size_t)b*384 + j] = v * (0.5f / 512.0f);
}

// ---------------- head: Linear(384,256)->BN(eval)->ReLU6->Linear(256,8) ------
__global__ __launch_bounds__(256)
void head_kernel(const float* __restrict__ fW1, const float* __restrict__ fb1,
                 const float* __restrict__ bng, const float* __restrict__ bnb,
                 const float* __restrict__ fW2, const float* __restrict__ fb2,
                 float* __restrict__ out)
{
    __shared__ float oms[384];
    __shared__ float hsh[256];
    int b = blockIdx.x, tid = threadIdx.x;
    for (int k = tid; k < 384; k += 256) oms[k] = g_scratch[OFF_OM + (size_t)b*384 + k];
    __syncthreads();
    float acc = fb1[tid];
    for (int k = 0; k < 384; k++) acc += oms[k] * fW1[(size_t)k*256 + tid];
    float scale = rsqrtf(1.0f + 1e-5f);
    float hv = acc * scale * bng[tid] + bnb[tid];
    hv = fminf(fmaxf(hv, 0.f), 6.f);
    hsh[tid] = hv;
    __syncthreads();
    if (tid < 8) {
        float a2 = fb2[tid];
        for (int k = 0; k < 256; k++) a2 += hsh[k] * fW2[k*8 + tid];
        out[b*8 + tid] = a2;
    }
}

// ---------------- host launcher ----------------
extern "C" void kernel_launch(void* const* d_in, const int* in_sizes, int n_in,
                              void* d_out, int out_size)
{
    (void)in_sizes; (void)n_in; (void)out_size;
    const float* text   = (const float*)d_in[0];
    const float* visual = (const float*)d_in[1];
    const float* audio  = (const float*)d_in[2];
    const float* fc1W = (const float*)d_in[3];
    const float* fc1b = (const float*)d_in[4];
    const float* fc2W = (const float*)d_in[5];
    const float* fc2b = (const float*)d_in[6];
    const float* fc3W = (const float*)d_in[7];
    const float* fc3b = (const float*)d_in[8];
    const float* Wq = (const float*)d_in[9];
    const float* bq = (const float*)d_in[10];
    const float* Wk = (const float*)d_in[11];
    const float* bk = (const float*)d_in[12];
    const float* Wv = (const float*)d_in[13];
    const float* bv = (const float*)d_in[14];
    const float* Wd = (const float*)d_in[15];
    const float* bd = (const float*)d_in[16];
    const float* lng = (const float*)d_in[17];
    const float* lnb = (const float*)d_in[18];
    const float* gWih = (const float*)d_in[19];
    const float* gWhh = (const float*)d_in[20];
    const float* gbih = (const float*)d_in[21];
    const float* gbhh = (const float*)d_in[22];
    const float* fW1 = (const float*)d_in[23];
    const float* fb1 = (const float*)d_in[24];
    const float* bng = (const float*)d_in[25];
    const float* bnb = (const float*)d_in[26];
    const float* fW2 = (const float*)d_in[27];
    const float* fb2 = (const float*)d_in[28];
    float* out = (float*)d_out;

    cudaFuncSetAttribute(attn_flash,
                         cudaFuncAttributeMaxDynamicSharedMemorySize, ATTN_SMEM);

    dim3 blk(256);

    // GRU weight transposes (independent; overlaps downstream launches' tails)
    transpose_w_kernel<<<12, 256>>>(gWih, gWhh);

    // input projections into t,v,a
    proj_gemm<<<RTOT/128, blk>>>(text,   fc1W, fc1b, 300, 0);
    proj_gemm<<<RTOT/128, blk>>>(visual, fc2W, fc2b, 35,  1);
    proj_gemm<<<RTOT/128, blk>>>(audio,  fc3W, fc3b, 74,  2);

    // all 18 QKV projections in one launch
    qkv_gemm<<<dim3(RTOT/128, 1, 18), blk>>>(Wq, Wk, Wv, bq, bk, bv);

    // V column sums, then all 6 attentions in one launch
    vsum_kernel<<<dim3(64, 2, 6), 64>>>();
    attn_flash<<<dim3(8, 128, 6), blk, ATTN_SMEM>>>();

    // out-proj + LN + average (two phases to avoid accumulation conflicts)
    epi_gemm<<<dim3(RTOT/128, 1, 3), blk>>>(Wd, bd, lng, lnb, 0);
    epi_gemm<<<dim3(RTOT/128, 1, 3), blk>>>(Wd, bd, lng, lnb, 1);

    // GRU input gates for all 6 directions in one launch
    gx_gemm<<<dim3(RTOT/128, 3, 6), blk>>>(gbih);

    // recurrence, pooling, head
    gru_kernel<<<384, 384>>>(gbhh);
    combine_kernel<<<64, 384>>>();
    head_kernel<<<64, 256>>>(fW1, fb1, bng, bnb, fW2, fb2, out);
}

// round 13
// speedup vs baseline: 1.0034x; 1.0034x over previous
#include <cuda_runtime.h>
#include <math.h>

// Problem constants
#define BB   64
#define SS   512
#define DD   128
#define DH   64
#define RTOT (BB*SS)                    // 32768 rows

static constexpr size_t SZ       = (size_t)RTOT * DD;      // 4194304 floats
static constexpr size_t OFF_T    = 0;                      // t,v,a at 0,1,2
static constexpr size_t OFF_QKV  = 3*SZ;                   // 18 buffers (unit*3 + {q,k,v})
static constexpr size_t OFF_CTX  = 21*SZ;                  // 6 buffers
static constexpr size_t OFF_OUT3 = 27*SZ;                  // ot, ov, oa
static constexpr size_t OFF_VSUM = 30*SZ;                  // [6][64][2][64]
static constexpr size_t OFF_GX   = OFF_VSUM + 49152;
static constexpr size_t GX_PER   = (size_t)RTOT * 384;     // 12582912
static constexpr size_t OFF_WIHT = OFF_GX + 6*GX_PER;      // 6 x [128][384]
static constexpr size_t OFF_WHHT = OFF_WIHT + 6*49152;
static constexpr size_t OFF_HSUM = OFF_WHHT + 6*49152;     // [6][64][128]
static constexpr size_t OFF_OM   = OFF_HSUM + 49152;       // [64][384]
static constexpr size_t SCRATCH_TOTAL = OFF_OM + 24576;

__device__ float g_scratch[SCRATCH_TOTAL];

// ---------------- packed fp32x2 FMA (FFMA2; ptxas never auto-generates) -------
__device__ __forceinline__ void ffma2(float2& d, float2 a, float2 b) {
    asm("fma.rn.f32x2 %0, %1, %2, %0;"
        : "+l"(reinterpret_cast<unsigned long long&>(d))
        : "l"(reinterpret_cast<unsigned long long&>(a)),
          "l"(reinterpret_cast<unsigned long long&>(b)));
}
__device__ __forceinline__ float2 dup2(float a) { return make_float2(a, a); }

// ---------------- shared GEMM core: 128x128 tile, BK=16, 256 thr, 8x8 micro ---
// acc[r][c] is float2 covering output cols tx*8 + 2c, +1.
__device__ __forceinline__ void gemm_core(
    const float* __restrict__ Arow,   // A + rowbase*K (row stride == K)
    int K,
    const float* __restrict__ Wp,     // W + nbase     (row stride == ldw)
    int ldw,
    float2 (&acc)[8][4],
    float* As, float* Ws, int tid)
{
    int tx = tid & 15, ty = tid >> 4;
    for (int k0 = 0; k0 < K; k0 += 16) {
#pragma unroll
        for (int p = 0; p < 8; p++) {
            int idx = tid + p*256;
            int r = idx >> 4, kk = idx & 15;
            int k = k0 + kk;
            As[r*17 + kk] = (k < K) ? Arow[(size_t)r*K + k] : 0.f;
        }
#pragma unroll
        for (int p = 0; p < 8; p++) {
            int idx = tid + p*256;
            int kk = idx >> 7, n = idx & 127;
            int k = k0 + kk;
            Ws[kk*128 + n] = (k < K) ? Wp[(size_t)k*ldw + n] : 0.f;
        }
        __syncthreads();
#pragma unroll
        for (int kk = 0; kk < 16; kk++) {
            float4 w0 = *(const float4*)&Ws[kk*128 + tx*8];
            float4 w1 = *(const float4*)&Ws[kk*128 + tx*8 + 4];
            float2 wv0 = make_float2(w0.x, w0.y);
            float2 wv1 = make_float2(w0.z, w0.w);
            float2 wv2 = make_float2(w1.x, w1.y);
            float2 wv3 = make_float2(w1.z, w1.w);
#pragma unroll
            for (int r = 0; r < 8; r++) {
                float2 aa = dup2(As[(ty*8 + r)*17 + kk]);
                ffma2(acc[r][0], aa, wv0);
                ffma2(acc[r][1], aa, wv1);
                ffma2(acc[r][2], aa, wv2);
                ffma2(acc[r][3], aa, wv3);
            }
        }
        __syncthreads();
    }
}

__device__ __forceinline__ void epi_plain(
    float2 (&acc)[8][4], const float* __restrict__ bias,
    float* __restrict__ C, int ldc, int rowbase, int nbase, int tid)
{
    int tx = tid & 15, ty = tid >> 4;
    float4 b0 = *(const float4*)&bias[nbase + tx*8];
    float4 b1 = *(const float4*)&bias[nbase + tx*8 + 4];
#pragma unroll
    for (int r = 0; r < 8; r++) {
        int row = rowbase + ty*8 + r;
        float* Cp = C + (size_t)row*ldc + nbase + tx*8;
        float4 o0 = make_float4(acc[r][0].x + b0.x, acc[r][0].y + b0.y,
                                acc[r][1].x + b0.z, acc[r][1].y + b0.w);
        float4 o1 = make_float4(acc[r][2].x + b1.x, acc[r][2].y + b1.y,
                                acc[r][3].x + b1.z, acc[r][3].y + b1.w);
        *(float4*)Cp       = o0;
        *(float4*)(Cp + 4) = o1;
    }
}

// ---------------- input projection GEMMs ----------------
__global__ __launch_bounds__(256, 2)
void proj_gemm(const float* __restrict__ A, const float* __restrict__ W,
               const float* __restrict__ bias, int K, int dst)
{
    __shared__ float As[128*17];
    __shared__ float Ws[16*128];
    int tid = threadIdx.x;
    int rowbase = blockIdx.x * 128;
    float2 acc[8][4];
#pragma unroll
    for (int r = 0; r < 8; r++)
#pragma unroll
        for (int c = 0; c < 4; c++) acc[r][c] = make_float2(0.f, 0.f);
    gemm_core(A + (size_t)rowbase*K, K, W, 128, acc, As, Ws, tid);
    epi_plain(acc, bias, g_scratch + OFF_T + (size_t)dst*SZ, 128, rowbase, 0, tid);
}

// ---------------- batched QKV GEMMs (z = unit*3 + which) ----------------
__global__ __launch_bounds__(256, 2)
void qkv_gemm(const float* __restrict__ Wq, const float* __restrict__ Wk,
              const float* __restrict__ Wv, const float* __restrict__ bq,
              const float* __restrict__ bk, const float* __restrict__ bv)
{
    __shared__ float As[128*17];
    __shared__ float Ws[16*128];
    const int qsel[6] = {0,2,0,1,1,2};
    const int ksel[6] = {2,0,1,0,2,1};
    int tid = threadIdx.x;
    int z = blockIdx.z;
    int unit = z / 3, which = z % 3;
    int src = (which == 0) ? qsel[unit] : ksel[unit];
    const float* A = g_scratch + OFF_T + (size_t)src*SZ;
    const float* W = ((which == 0) ? Wq : (which == 1) ? Wk : Wv) + (size_t)unit*16384;
    const float* b = ((which == 0) ? bq : (which == 1) ? bk : bv) + unit*128;
    float* C = g_scratch + OFF_QKV + (size_t)z*SZ;
    int rowbase = blockIdx.x * 128;
    float2 acc[8][4];
#pragma unroll
    for (int r = 0; r < 8; r++)
#pragma unroll
        for (int c = 0; c < 4; c++) acc[r][c] = make_float2(0.f, 0.f);
    gemm_core(A + (size_t)rowbase*128, 128, W, 128, acc, As, Ws, tid);
    epi_plain(acc, b, C, 128, rowbase, 0, tid);
}

// ---------------- V column sums (for ctx = Vsum - softmax@V) ----------------
__global__ void vsum_kernel()
{
    int b = blockIdx.x, h = blockIdx.y, u = blockIdx.z, d = threadIdx.x;
    const float* V = g_scratch + OFF_QKV + (size_t)(u*3 + 2)*SZ
                   + (size_t)b*SS*DD + h*DH + d;
    float s = 0.f;
#pragma unroll 8
    for (int k = 0; k < SS; k++) s += V[(size_t)k*DD];
    g_scratch[OFF_VSUM + (((size_t)u*64 + b)*2 + h)*64 + d] = s;
}

// ---------------- batched flash attention ----------------
// grid = (8 q-tiles, B*H=128, 6 units), block = 256, dyn smem = 4*64*68*4 B.
// ctx = Vsum - softmax(QK^T/8)@V  (exactly (1 - softmax)@V).
#define ATTN_SMEM (4*64*68*4)

__global__ __launch_bounds__(256, 2)
void attn_flash()
{
    extern __shared__ float sm[];
    float* Qs = sm;              // [64][68]  (row-major, q rows)
    float* Ks = sm + 64*68;      // [64][68]  TRANSPOSED: Ks[d][k]
    float* Vs = sm + 2*64*68;    // [64][68]  (row = k)
    float* Ps = sm + 3*64*68;    // [64][68]  (row = q, col = k)

    int tid = threadIdx.x;
    int u = blockIdx.z;
    int bh = blockIdx.y;
    int b = bh >> 1, h = bh & 1;
    int q0 = blockIdx.x * 64;

    const float* Qb = g_scratch + OFF_QKV + (size_t)(u*3 + 0)*SZ;
    const float* Kb = g_scratch + OFF_QKV + (size_t)(u*3 + 1)*SZ;
    const float* Vb = g_scratch + OFF_QKV + (size_t)(u*3 + 2)*SZ;
    size_t baseQ  = ((size_t)b*SS + q0)*DD + h*DH;
    size_t baseKV = ((size_t)b*SS)*DD + h*DH;

#pragma unroll
    for (int p = 0; p < 16; p++) {
        int idx = tid + p*256;
        int r = idx >> 6, c = idx & 63;
        Qs[r*68 + c] = Qb[baseQ + (size_t)r*DD + c];
    }

    int tx = tid & 15;   // 4 output d-cols / 4 k-cols
    int ty = tid >> 4;   // 4 q rows

    float2 oacc[4][2];
    float m[4], l[4];
#pragma unroll
    for (int i = 0; i < 4; i++) {
        oacc[i][0] = make_float2(0.f, 0.f);
        oacc[i][1] = make_float2(0.f, 0.f);
        m[i] = -1e30f; l[i] = 0.f;
    }

    for (int kt = 0; kt < 8; kt++) {
        __syncthreads();                       // prev PV done with Vs/Ps
#pragma unroll
        for (int p = 0; p < 16; p++) {
            int idx = tid + p*256;
            int r = idx >> 6, c = idx & 63;
            size_t g = baseKV + (size_t)(kt*64 + r)*DD + c;
            Ks[c*68 + r] = Kb[g];              // transposed store
            Vs[r*68 + c] = Vb[g];
        }
        __syncthreads();

        // scores: s2[i][0]=(j0,j1), s2[i][1]=(j2,j3)
        float2 s2[4][2];
#pragma unroll
        for (int i = 0; i < 4; i++) { s2[i][0] = make_float2(0.f,0.f); s2[i][1] = make_float2(0.f,0.f); }
#pragma unroll 8
        for (int d = 0; d < 64; d++) {
            float4 k4 = *(const float4*)&Ks[d*68 + tx*4];
            float2 ka = make_float2(k4.x, k4.y);
            float2 kb2 = make_float2(k4.z, k4.w);
#pragma unroll
            for (int i = 0; i < 4; i++) {
                float2 qq = dup2(Qs[(ty*4 + i)*68 + d]);
                ffma2(s2[i][0], qq, ka);
                ffma2(s2[i][1], qq, kb2);
            }
        }

        // online softmax update + stash P
#pragma unroll
        for (int i = 0; i < 4; i++) {
            float s0 = s2[i][0].x * 0.125f;
            float s1 = s2[i][0].y * 0.125f;
            float s2v = s2[i][1].x * 0.125f;
            float s3 = s2[i][1].y * 0.125f;
            float tm = fmaxf(fmaxf(s0, s1), fmaxf(s2v, s3));
#pragma unroll
            for (int off = 8; off >= 1; off >>= 1)
                tm = fmaxf(tm, __shfl_xor_sync(0xffffffffu, tm, off));
            float mn = fmaxf(m[i], tm);
            float corr = __expf(m[i] - mn);
            float p0 = __expf(s0 - mn);
            float p1 = __expf(s1 - mn);
            float p2 = __expf(s2v - mn);
            float p3 = __expf(s3 - mn);
            float ps = p0 + p1 + p2 + p3;
#pragma unroll
            for (int off = 8; off >= 1; off >>= 1)
                ps += __shfl_xor_sync(0xffffffffu, ps, off);
            l[i] = l[i]*corr + ps;
            oacc[i][0].x *= corr; oacc[i][0].y *= corr;
            oacc[i][1].x *= corr; oacc[i][1].y *= corr;
            m[i] = mn;
            *(float4*)&Ps[(ty*4 + i)*68 + tx*4] = make_float4(p0, p1, p2, p3);
        }
        __syncthreads();                       // Ps visible

        // PV: oacc[i] += P[row i] @ Vtile
#pragma unroll 4
        for (int k4i = 0; k4i < 16; k4i++) {
            float4 p4[4];
#pragma unroll
            for (int i = 0; i < 4; i++)
                p4[i] = *(const float4*)&Ps[(ty*4 + i)*68 + k4i*4];
#pragma unroll
            for (int kk = 0; kk < 4; kk++) {
                float4 v4 = *(const float4*)&Vs[(k4i*4 + kk)*68 + tx*4];
                float2 va = make_float2(v4.x, v4.y);
                float2 vb2 = make_float2(v4.z, v4.w);
#pragma unroll
                for (int i = 0; i < 4; i++) {
                    float pk = (kk == 0) ? p4[i].x : (kk == 1) ? p4[i].y
                             : (kk == 2) ? p4[i].z : p4[i].w;
                    float2 pp = dup2(pk);
                    ffma2(oacc[i][0], pp, va);
                    ffma2(oacc[i][1], pp, vb2);
                }
            }
        }
    }

    float4 vs4 = *(const float4*)&g_scratch[OFF_VSUM + (((size_t)u*64 + b)*2 + h)*64 + tx*4];
    float* Cb = g_scratch + OFF_CTX + (size_t)u*SZ;
#pragma unroll
    for (int i = 0; i < 4; i++) {
        float inv = 1.f / l[i];
        size_t idx = ((size_t)b*SS + q0 + ty*4 + i)*DD + h*DH + tx*4;
        float4 o;
        o.x = vs4.x - oacc[i][0].x * inv;
        o.y = vs4.y - oacc[i][0].y * inv;
        o.z = vs4.z - oacc[i][1].x * inv;
        o.w = vs4.w - oacc[i][1].y * inv;
        *(float4*)&Cb[idx] = o;
    }
}

// ---------------- batched out-proj + LayerNorm + 0.5*accumulate --------------
// phase 0: units 0,1,2 (beta=0); phase 1: units 3,4,5 (beta=1)
__global__ __launch_bounds__(256, 2)
void epi_gemm(const float* __restrict__ Wd, const float* __restrict__ bd,
              const float* __restrict__ lng, const float* __restrict__ lnb,
              int phase)
{
    __shared__ float As[128*17];
    __shared__ float Ws[16*128];
    const int accsel[6] = {2,0,1,0,2,1};   // -> {ot,ov,oa} index
    int tid = threadIdx.x;
    int unit = phase*3 + blockIdx.z;
    const float* A = g_scratch + OFF_CTX + (size_t)unit*SZ;
    float* C = g_scratch + OFF_OUT3 + (size_t)accsel[unit]*SZ;
    const float* bias = bd + unit*128;
    const float* lg = lng + unit*128;
    const float* lb = lnb + unit*128;
    int rowbase = blockIdx.x * 128;

    float2 acc[8][4];
#pragma unroll
    for (int r = 0; r < 8; r++)
#pragma unroll
        for (int c = 0; c < 4; c++) acc[r][c] = make_float2(0.f, 0.f);
    gemm_core(A + (size_t)rowbase*128, 128, Wd + (size_t)unit*16384, 128, acc, As, Ws, tid);

    int tx = tid & 15, ty = tid >> 4;
    const float inv = 1.0f / 128.0f;
#pragma unroll
    for (int r = 0; r < 8; r++) {
        float vals[8];
        float s = 0.f, s2 = 0.f;
#pragma unroll
        for (int c = 0; c < 8; c++) {
            float2 a2 = acc[r][c >> 1];
            float vv = ((c & 1) ? a2.y : a2.x) + bias[tx*8 + c];
            vals[c] = vv; s += vv; s2 += vv*vv;
        }
#pragma unroll
        for (int off = 8; off >= 1; off >>= 1) {
            s  += __shfl_xor_sync(0xffffffffu, s,  off);
            s2 += __shfl_xor_sync(0xffffffffu, s2, off);
        }
        float mean = s * inv;
        float var  = s2 * inv - mean*mean;
        float rstd = rsqrtf(var + 1e-5f);
        int row = rowbase + ty*8 + r;
#pragma unroll
        for (int c = 0; c < 8; c++) {
            int col = tx*8 + c;
            float o = (vals[c] - mean) * rstd * lg[col] + lb[col];
            size_t idx = (size_t)row*128 + col;
            if (phase == 0) C[idx] = 0.5f * o;
            else            C[idx] = C[idx] + 0.5f * o;
        }
    }
}

// ---------------- batched GRU input-gate GEMMs (z = dir6) ----------------
__global__ __launch_bounds__(256, 2)
void gx_gemm(const float* __restrict__ gbih)
{
    __shared__ float As[128*17];
    __shared__ float Ws[16*128];
    int tid = threadIdx.x;
    int z = blockIdx.z;                         // dir6
    const float* A = g_scratch + OFF_OUT3 + (size_t)(z >> 1)*SZ;
    const float* Wp = g_scratch + OFF_WIHT + (size_t)z*49152;
    float* C = g_scratch + OFF_GX + (size_t)z*GX_PER;
    int rowbase = blockIdx.x * 128;
    int nbase   = blockIdx.y * 128;

    float2 acc[8][4];
#pragma unroll
    for (int r = 0; r < 8; r++)
#pragma unroll
        for (int c = 0; c < 4; c++) acc[r][c] = make_float2(0.f, 0.f);
    gemm_core(A + (size_t)rowbase*128, 128, Wp + nbase, 384, acc, As, Ws, tid);
    epi_plain(acc, gbih + z*384, C, 384, rowbase, nbase, tid);
}

// ---------------- GRU weight transposes ----------------
__global__ void transpose_w_kernel(const float* __restrict__ gWih,
                                   const float* __restrict__ gWhh)
{
    int mIdx = blockIdx.x;                 // 0..11
    const float* src = (mIdx < 6 ? gWih : gWhh) + (size_t)(mIdx % 6)*384*128;
    float* dst = g_scratch + (mIdx < 6 ? OFF_WIHT : OFF_WHHT) + (size_t)(mIdx % 6)*49152;
    for (int idx = threadIdx.x; idx < 128*384; idx += blockDim.x) {
        int k = idx / 384, n = idx % 384;
        dst[idx] = src[(size_t)n*128 + k];
    }
}

// ---------------- GRU recurrence (384 chains) ----------------
__global__ __launch_bounds__(384)
void gru_kernel(const float* __restrict__ gbhh)
{
    int dir6 = blockIdx.x >> 6;
    int b    = blockIdx.x & 63;
    int j    = threadIdx.x;

    const float* wp = g_scratch + OFF_WHHT + (size_t)dir6*49152 + j;
    float2 w2[64];
#pragma unroll
    for (int k = 0; k < 64; k++)
        w2[k] = make_float2(wp[(size_t)(2*k)*384], wp[(size_t)(2*k + 1)*384]);
    float bh = gbhh[dir6*384 + j];

    __shared__ float h[128];
    __shared__ float gh[384];
    __shared__ float gxs[384];
    __shared__ float hs[128];
    if (j < 128) { h[j] = 0.f; hs[j] = 0.f; }

    const float* gxb = g_scratch + OFF_GX + (size_t)dir6*GX_PER + (size_t)b*SS*384;
    int rev = dir6 & 1;
    const float2* h2 = (const float2*)h;

    for (int step = 0; step < SS; step++) {
        int t = rev ? (SS - 1 - step) : step;
        float gxv = gxb[(size_t)t*384 + j];     // prefetch (latency hidden by matvec)
        __syncthreads();                        // h ready; prev gxs reads done
        gxs[j] = gxv;
        float2 acc = make_float2(0.f, 0.f);
#pragma unroll
        for (int k = 0; k < 64; k++) ffma2(acc, w2[k], h2[k]);
        gh[j] = acc.x + acc.y + bh;
        __syncthreads();                        // gh + gxs complete
        if (j < 128) {
            float r  = 1.f / (1.f + __expf(-(gxs[j]       + gh[j])));
            float z  = 1.f / (1.f + __expf(-(gxs[128 + j] + gh[128 + j])));
            float n  = tanhf(gxs[256 + j] + r * gh[256 + j]);
            float hn = (1.f - z)*n + z*h[j];
            h[j]  = hn;
            hs[j] += hn;
        }
    }
    __syncthreads();
    if (j < 128) g_scratch[OFF_HSUM + ((size_t)dir6*64 + b)*128 + j] = hs[j];
}

// ---------------- combine h-sums -> pooled features [64,384] ----------------
__global__ void combine_kernel()
{
    int b = blockIdx.x;
    int j = threadIdx.x;          // 0..383
    int seg = j >> 7, i = j & 127;
    float v = g_scratch[OFF_HSUM + ((size_t)seg*64 + b)*128 + i]
            + g_scratch[OFF_HSUM + ((size_t)(seg + 3)*64 + b)*128 + i];
    g_scratch[OFF_OM + (size_t)b*384 + j] = v * (0.5f / 512.0f);
}

// ---------------- head: Linear(384,256)->BN(eval)->ReLU6->Linear(256,8) ------
__global__ __launch_bounds__(256)
void head_kernel(const float* __restrict__ fW1, const float* __restrict__ fb1,
                 const float* __restrict__ bng, const float* __restrict__ bnb,
                 const float* __restrict__ fW2, const float* __restrict__ fb2,
                 float* __restrict__ out)
{
    __shared__ float oms[384];
    __shared__ float hsh[256];
    int b = blockIdx.x, tid = threadIdx.x;
    for (int k = tid; k < 384; k += 256) oms[k] = g_scratch[OFF_OM + (size_t)b*384 + k];
    __syncthreads();
    float acc = fb1[tid];
    for (int k = 0; k < 384; k++) acc += oms[k] * fW1[(size_t)k*256 + tid];
    float scale = rsqrtf(1.0f + 1e-5f);
    float hv = acc * scale * bng[tid] + bnb[tid];
    hv = fminf(fmaxf(hv, 0.f), 6.f);
    hsh[tid] = hv;
    __syncthreads();
    if (tid < 8) {
        float a2 = fb2[tid];
        for (int k = 0; k < 256; k++) a2 += hsh[k] * fW2[k*8 + tid];
        out[b*8 + tid] = a2;
    }
}

// ---------------- host launcher ----------------
extern "C" void kernel_launch(void* const* d_in, const int* in_sizes, int n_in,
                              void* d_out, int out_size)
{
    (void)in_sizes; (void)n_in; (void)out_size;
    const float* text   = (const float*)d_in[0];
    const float* visual = (const float*)d_in[1];
    const float* audio  = (const float*)d_in[2];
    const float* fc1W = (const float*)d_in[3];
    const float* fc1b = (const float*)d_in[4];
    const float* fc2W = (const float*)d_in[5];
    const float* fc2b = (const float*)d_in[6];
    const float* fc3W = (const float*)d_in[7];
    const float* fc3b = (const float*)d_in[8];
    const float* Wq = (const float*)d_in[9];
    const float* bq = (const float*)d_in[10];
    const float* Wk = (const float*)d_in[11];
    const float* bk = (const float*)d_in[12];
    const float* Wv = (const float*)d_in[13];
    const float* bv = (const float*)d_in[14];
    const float* Wd = (const float*)d_in[15];
    const float* bd = (const float*)d_in[16];
    const float* lng = (const float*)d_in[17];
    const float* lnb = (const float*)d_in[18];
    const float* gWih = (const float*)d_in[19];
    const float* gWhh = (const float*)d_in[20];
    const float* gbih = (const float*)d_in[21];
    const float* gbhh = (const float*)d_in[22];
    const float* fW1 = (const float*)d_in[23];
    const float* fb1 = (const float*)d_in[24];
    const float* bng = (const float*)d_in[25];
    const float* bnb = (const float*)d_in[26];
    const float* fW2 = (const float*)d_in[27];
    const float* fb2 = (const float*)d_in[28];
    float* out = (float*)d_out;

    cudaFuncSetAttribute(attn_flash,
                         cudaFuncAttributeMaxDynamicSharedMemorySize, ATTN_SMEM);

    dim3 blk(256);

    // GRU weight transposes (independent; overlaps downstream launches' tails)
    transpose_w_kernel<<<12, 256>>>(gWih, gWhh);

    // input projections into t,v,a
    proj_gemm<<<RTOT/128, blk>>>(text,   fc1W, fc1b, 300, 0);
    proj_gemm<<<RTOT/128, blk>>>(visual, fc2W, fc2b, 35,  1);
    proj_gemm<<<RTOT/128, blk>>>(audio,  fc3W, fc3b, 74,  2);

    // all 18 QKV projections in one launch
    qkv_gemm<<<dim3(RTOT/128, 1, 18), blk>>>(Wq, Wk, Wv, bq, bk, bv);

    // V column sums, then all 6 attentions in one launch
    vsum_kernel<<<dim3(64, 2, 6), 64>>>();
    attn_flash<<<dim3(8, 128, 6), blk, ATTN_SMEM>>>();

    // out-proj + LN + average (two phases to avoid accumulation conflicts)
    epi_gemm<<<dim3(RTOT/128, 1, 3), blk>>>(Wd, bd, lng, lnb, 0);
    epi_gemm<<<dim3(RTOT/128, 1, 3), blk>>>(Wd, bd, lng, lnb, 1);

    // GRU input gates for all 6 directions in one launch
    gx_gemm<<<dim3(RTOT/128, 3, 6), blk>>>(gbih);

    // recurrence, pooling, head
    gru_kernel<<<384, 384>>>(gbhh);
    combine_kernel<<<64, 384>>>();
    head_kernel<<<64, 256>>>(fW1, fb1, bng, bnb, fW2, fb2, out);
}

// round 16
// speedup vs baseline: 1.2111x; 1.2070x over previous
#include <cuda_runtime.h>
#include <cuda_bf16.h>
#include <math.h>
#include <stdint.h>

#define BB   64
#define SS   512
#define DD   128
#define DH   64
#define RTOT (BB*SS)

static constexpr size_t SZ       = (size_t)RTOT * DD;
static constexpr size_t OFF_T    = 0;
static constexpr size_t OFF_QKV  = 3*SZ;
static constexpr size_t OFF_CTX  = 21*SZ;
static constexpr size_t OFF_OUT3 = 27*SZ;
static constexpr size_t OFF_VSUM = 30*SZ;
static constexpr size_t OFF_GX   = OFF_VSUM + 49152;
static constexpr size_t GX_PER   = (size_t)RTOT * 384;
static constexpr size_t OFF_WHHT = OFF_GX + 6*GX_PER;
static constexpr size_t OFF_HSUM = OFF_WHHT + 6*49152;
static constexpr size_t OFF_OM   = OFF_HSUM + 49152;
static constexpr size_t SCRATCH_TOTAL = OFF_OM + 24576;

__device__ float g_scratch[SCRATCH_TOTAL];

// bf16 hi/lo weight images in B-fragment order.
// Per 16-K chunk: uint32[2048] = [1024 hi | 1024 lo]; word (n, w) = cols k=2w,2w+1 of B-row n.
static constexpr size_t IMG_QKVD = 0;                                // 24 tiles x 8 ch x 2048
static constexpr size_t IMG_WIH  = IMG_QKVD + (size_t)24*16384;      // 18 tiles x 8 ch
static constexpr size_t IMG_PROJ = IMG_WIH  + (size_t)18*16384;      // 19+3+5 = 27 chunks
static constexpr size_t IMG_TOTAL = IMG_PROJ + (size_t)27*2048;

__device__ uint32_t g_img[IMG_TOTAL];

// ---------------- packed fp32x2 FMA ----------------
__device__ __forceinline__ void ffma2(float2& d, float2 a, float2 b) {
    asm("fma.rn.f32x2 %0, %1, %2, %0;"
        : "+l"(reinterpret_cast<unsigned long long&>(d))
        : "l"(reinterpret_cast<unsigned long long&>(a)),
          "l"(reinterpret_cast<unsigned long long&>(b)));
}
__device__ __forceinline__ float2 dup2(float a) { return make_float2(a, a); }

// ---------------- bf16 split helpers ----------------
__device__ __forceinline__ uint32_t pack_hi(float f0, float f1) {
    __nv_bfloat16 h0 = __float2bfloat16(f0), h1 = __float2bfloat16(f1);
    return (uint32_t)__bfloat16_as_ushort(h0) | ((uint32_t)__bfloat16_as_ushort(h1) << 16);
}
__device__ __forceinline__ uint32_t pack_lo(float f0, float f1) {
    __nv_bfloat16 h0 = __float2bfloat16(f0), h1 = __float2bfloat16(f1);
    __nv_bfloat16 b0 = __float2bfloat16(f0 - __bfloat162float(h0));
    __nv_bfloat16 b1 = __float2bfloat16(f1 - __bfloat162float(h1));
    return (uint32_t)__bfloat16_as_ushort(b0) | ((uint32_t)__bfloat16_as_ushort(b1) << 16);
}

// ---------------- mma.sync m16n8k16 row.col f32.bf16 ----------------
__device__ __forceinline__ void hmma(float (&d)[4], const uint32_t (&a)[4], const uint32_t (&b)[2]) {
    asm volatile("mma.sync.aligned.m16n8k16.row.col.f32.bf16.bf16.f32 "
        "{%0,%1,%2,%3}, {%4,%5,%6,%7}, {%8,%9}, {%0,%1,%2,%3};"
        : "+f"(d[0]), "+f"(d[1]), "+f"(d[2]), "+f"(d[3])
        : "r"(a[0]), "r"(a[1]), "r"(a[2]), "r"(a[3]), "r"(b[0]), "r"(b[1]));
}

// ---------------- prepack kernels ----------------
// square (Wq 0-5, Wk 6-11, Wv 12-17, Wd 18-23): B[n][k] = W[k][n]
__global__ __launch_bounds__(128)
void prepack_sq(const float* __restrict__ Wq, const float* __restrict__ Wk,
                const float* __restrict__ Wv, const float* __restrict__ Wd)
{
    int m = blockIdx.x, n = threadIdx.x;
    const float* W = (m < 6) ? Wq + (size_t)m*16384 : (m < 12) ? Wk + (size_t)(m-6)*16384
                   : (m < 18) ? Wv + (size_t)(m-12)*16384 : Wd + (size_t)(m-18)*16384;
    uint32_t* img = g_img + IMG_QKVD + (size_t)m*16384;
    for (int c = 0; c < 8; c++)
        for (int w = 0; w < 8; w++) {
            int k = c*16 + 2*w;
            float f0 = W[(size_t)k*128 + n], f1 = W[(size_t)(k+1)*128 + n];
            img[c*2048 + n*8 + w]        = pack_hi(f0, f1);
            img[c*2048 + 1024 + n*8 + w] = pack_lo(f0, f1);
        }
}

// Wih (gx = x @ Wih^T): B[n][k] = Wih[n][k] (natural rows)
__global__ __launch_bounds__(128)
void prepack_wih(const float* __restrict__ gWih)
{
    int m = blockIdx.x, n = threadIdx.x;   // m = dir*3 + ntile
    const float* src = gWih + (size_t)(m/3)*384*128 + (size_t)(m%3)*128*128 + (size_t)n*128;
    uint32_t* img = g_img + IMG_WIH + (size_t)m*16384;
    for (int c = 0; c < 8; c++)
        for (int w = 0; w < 8; w++) {
            int k = c*16 + 2*w;
            img[c*2048 + n*8 + w]        = pack_hi(src[k], src[k+1]);
            img[c*2048 + 1024 + n*8 + w] = pack_lo(src[k], src[k+1]);
        }
}

// proj (transpose + zero-pad K): fc1 19 chunks, fc2 3, fc3 5
__global__ __launch_bounds__(128)
void prepack_proj(const float* __restrict__ fc1W, const float* __restrict__ fc2W,
                  const float* __restrict__ fc3W)
{
    int blk = blockIdx.x, n = threadIdx.x;
    int z, c;
    if (blk < 19)      { z = 0; c = blk; }
    else if (blk < 22) { z = 1; c = blk - 19; }
    else               { z = 2; c = blk - 22; }
    const int Kt[3] = {300, 35, 74};
    const size_t base[3] = {0, (size_t)19*2048, (size_t)22*2048};
    int K = Kt[z];
    const float* W = (z == 0) ? fc1W : (z == 1) ? fc2W : fc3W;
    uint32_t* img = g_img + IMG_PROJ + base[z] + (size_t)c*2048;
    for (int w = 0; w < 8; w++) {
        int k = c*16 + 2*w;
        float f0 = (k     < K) ? W[(size_t)k*128 + n]     : 0.f;
        float f1 = (k + 1 < K) ? W[(size_t)(k+1)*128 + n] : 0.f;
        img[n*8 + w]        = pack_hi(f0, f1);
        img[1024 + n*8 + w] = pack_lo(f0, f1);
    }
}

// ---------------- MMA GEMM core: 128x128 tile, 8 warps, warp tile 64x32 -------
// smem word arrays [128][8]; acc[i][j][4] covers rows wr*64+i*16+g(,+8), cols wc*32+j*8+tig*2(,+1)
__device__ __forceinline__ void mm_core(const float* __restrict__ A, int lda, int K,
                                        int nc, int vec, const uint32_t* __restrict__ img,
                                        uint32_t* sAh, uint32_t* sAl,
                                        uint32_t* sBh, uint32_t* sBl,
                                        float (&acc)[4][4][4])
{
    int tid = threadIdx.x;
    int lane = tid & 31, wid = tid >> 5;
    int g = lane >> 2, tig = lane & 3;
    int wr = wid & 1, wc = wid >> 1;
    int srow = tid >> 1, shalf = tid & 1;
    const uint4* img4 = (const uint4*)img;

    float f[8];
    uint4 pbh, pbl;
    {   // prefetch chunk 0
        int k0 = shalf*8;
        if (vec && k0 + 8 <= K) {
            float4 x = *(const float4*)&A[(size_t)srow*lda + k0];
            float4 y = *(const float4*)&A[(size_t)srow*lda + k0 + 4];
            f[0]=x.x; f[1]=x.y; f[2]=x.z; f[3]=x.w; f[4]=y.x; f[5]=y.y; f[6]=y.z; f[7]=y.w;
        } else {
#pragma unroll
            for (int i = 0; i < 8; i++) { int k = k0+i; f[i] = (k < K) ? A[(size_t)srow*lda + k] : 0.f; }
        }
        pbh = img4[tid];
        pbl = img4[256 + tid];
    }

    for (int c = 0; c < nc; c++) {
        *(uint4*)&sAh[srow*8 + shalf*4] = make_uint4(pack_hi(f[0],f[1]), pack_hi(f[2],f[3]),
                                                     pack_hi(f[4],f[5]), pack_hi(f[6],f[7]));
        *(uint4*)&sAl[srow*8 + shalf*4] = make_uint4(pack_lo(f[0],f[1]), pack_lo(f[2],f[3]),
                                                     pack_lo(f[4],f[5]), pack_lo(f[6],f[7]));
        ((uint4*)sBh)[tid] = pbh;
        ((uint4*)sBl)[tid] = pbl;
        __syncthreads();

        if (c + 1 < nc) {   // prefetch next chunk while computing
            int k0 = (c+1)*16 + shalf*8;
            if (vec && k0 + 8 <= K) {
                float4 x = *(const float4*)&A[(size_t)srow*lda + k0];
                float4 y = *(const float4*)&A[(size_t)srow*lda + k0 + 4];
                f[0]=x.x; f[1]=x.y; f[2]=x.z; f[3]=x.w; f[4]=y.x; f[5]=y.y; f[6]=y.z; f[7]=y.w;
            } else {
#pragma unroll
                for (int i = 0; i < 8; i++) { int k = k0+i; f[i] = (k < K) ? A[(size_t)srow*lda + k] : 0.f; }
            }
            pbh = img4[(size_t)(c+1)*512 + tid];
            pbl = img4[(size_t)(c+1)*512 + 256 + tid];
        }

        uint32_t ah[4][4], al[4][4];
#pragma unroll
        for (int i = 0; i < 4; i++) {
            int r0 = (wr*64 + i*16 + g)*8;
            ah[i][0] = sAh[r0+tig];   ah[i][1] = sAh[r0+64+tig];
            ah[i][2] = sAh[r0+4+tig]; ah[i][3] = sAh[r0+68+tig];
            al[i][0] = sAl[r0+tig];   al[i][1] = sAl[r0+64+tig];
            al[i][2] = sAl[r0+4+tig]; al[i][3] = sAl[r0+68+tig];
        }
#pragma unroll
        for (int j = 0; j < 4; j++) {
            int nb = (wc*32 + j*8 + g)*8;
            uint32_t bh[2] = {sBh[nb+tig], sBh[nb+4+tig]};
            uint32_t bl[2] = {sBl[nb+tig], sBl[nb+4+tig]};
#pragma unroll
            for (int i = 0; i < 4; i++) {
                hmma(acc[i][j], ah[i], bh);
                hmma(acc[i][j], al[i], bh);
                hmma(acc[i][j], ah[i], bl);
            }
        }
        __syncthreads();
    }
}

__device__ __forceinline__ void mm_epi_plain(float (&acc)[4][4][4], const float* sbias,
                                             float* __restrict__ C, int ldc,
                                             int rowbase, int nbase)
{
    int tid = threadIdx.x;
    int lane = tid & 31, wid = tid >> 5;
    int g = lane >> 2, tig = lane & 3;
    int wr = wid & 1, wc = wid >> 1;
#pragma unroll
    for (int i = 0; i < 4; i++) {
        int r0 = rowbase + wr*64 + i*16 + g;
#pragma unroll
        for (int j = 0; j < 4; j++) {
            int lc = wc*32 + j*8 + tig*2;
            float b0 = sbias[lc], b1 = sbias[lc+1];
            *(float2*)(C + (size_t)r0*ldc + nbase + lc)     = make_float2(acc[i][j][0]+b0, acc[i][j][1]+b1);
            *(float2*)(C + (size_t)(r0+8)*ldc + nbase + lc) = make_float2(acc[i][j][2]+b0, acc[i][j][3]+b1);
        }
    }
}

#define MM_ACC_INIT float acc[4][4][4]; \
    _Pragma("unroll") for (int i=0;i<4;i++) _Pragma("unroll") for (int j=0;j<4;j++) \
    _Pragma("unroll") for (int q=0;q<4;q++) acc[i][j][q]=0.f;

// ---------------- GEMM kernels ----------------
__global__ __launch_bounds__(256)
void mm_proj(const float* __restrict__ a0, const float* __restrict__ a1,
             const float* __restrict__ a2, const float* __restrict__ b0,
             const float* __restrict__ b1, const float* __restrict__ b2)
{
    __shared__ uint32_t sAh[1024], sAl[1024], sBh[1024], sBl[1024];
    __shared__ float sbias[128];
    const int Kt[3] = {300, 35, 74};
    const int nct[3] = {19, 3, 5};
    const size_t base[3] = {0, (size_t)19*2048, (size_t)22*2048};
    int tid = threadIdx.x, z = blockIdx.z;
    int rowbase = blockIdx.x * 128;
    int K = Kt[z];
    const float* A = ((z == 0) ? a0 : (z == 1) ? a1 : a2) + (size_t)rowbase*K;
    if (tid < 128) sbias[tid] = ((z == 0) ? b0 : (z == 1) ? b1 : b2)[tid];
    MM_ACC_INIT
    mm_core(A, K, K, nct[z], (z == 0) ? 1 : 0, g_img + IMG_PROJ + base[z], sAh, sAl, sBh, sBl, acc);
    mm_epi_plain(acc, sbias, g_scratch + OFF_T + (size_t)z*SZ, 128, rowbase, 0);
}

__global__ __launch_bounds__(256)
void mm_qkv(const float* __restrict__ bq, const float* __restrict__ bk,
            const float* __restrict__ bv)
{
    __shared__ uint32_t sAh[1024], sAl[1024], sBh[1024], sBl[1024];
    __shared__ float sbias[128];
    const int qsel[6] = {0,2,0,1,1,2};
    const int ksel[6] = {2,0,1,0,2,1};
    int tid = threadIdx.x, z = blockIdx.z;
    int unit = z / 3, which = z % 3;
    int src = (which == 0) ? qsel[unit] : ksel[unit];
    int rowbase = blockIdx.x * 128;
    const float* A = g_scratch + OFF_T + (size_t)src*SZ + (size_t)rowbase*128;
    if (tid < 128) sbias[tid] = (((which == 0) ? bq : (which == 1) ? bk : bv) + unit*128)[tid];
    MM_ACC_INIT
    mm_core(A, 128, 128, 8, 1, g_img + IMG_QKVD + (size_t)(which*6 + unit)*16384,
            sAh, sAl, sBh, sBl, acc);
    mm_epi_plain(acc, sbias, g_scratch + OFF_QKV + (size_t)z*SZ, 128, rowbase, 0);
}

__global__ __launch_bounds__(256)
void mm_gx(const float* __restrict__ gbih)
{
    __shared__ uint32_t sAh[1024], sAl[1024], sBh[1024], sBl[1024];
    __shared__ float sbias[128];
    int tid = threadIdx.x;
    int dir = blockIdx.z, ntile = blockIdx.y;
    int rowbase = blockIdx.x * 128;
    int nbase = ntile*128;
    const float* A = g_scratch + OFF_OUT3 + (size_t)(dir >> 1)*SZ + (size_t)rowbase*128;
    if (tid < 128) sbias[tid] = gbih[dir*384 + nbase + tid];
    MM_ACC_INIT
    mm_core(A, 128, 128, 8, 1, g_img + IMG_WIH + (size_t)(dir*3 + ntile)*16384,
            sAh, sAl, sBh, sBl, acc);
    mm_epi_plain(acc, sbias, g_scratch + OFF_GX + (size_t)dir*GX_PER, 384, rowbase, nbase);
}

// out-proj + LayerNorm + 0.5*accumulate (phase 0: units 0-2 write, 1: 3-5 accumulate)
__global__ __launch_bounds__(256)
void mm_ln(const float* __restrict__ bd, const float* __restrict__ lng,
           const float* __restrict__ lnb, int phase)
{
    __shared__ uint32_t sAh[1024], sAl[1024], sBh[1024], sBl[1024];
    __shared__ float sbias[128], slg[128], slb[128];
    __shared__ float ssum[512], ssum2[512];
    __shared__ float smean[128], srstd[128];
    const int accsel[6] = {2,0,1,0,2,1};
    int tid = threadIdx.x;
    int unit = phase*3 + blockIdx.z;
    int rowbase = blockIdx.x * 128;
    const float* A = g_scratch + OFF_CTX + (size_t)unit*SZ + (size_t)rowbase*128;
    float* C = g_scratch + OFF_OUT3 + (size_t)accsel[unit]*SZ;
    if (tid < 128) {
        sbias[tid] = bd[unit*128 + tid];
        slg[tid]   = lng[unit*128 + tid];
        slb[tid]   = lnb[unit*128 + tid];
    }
    MM_ACC_INIT
    mm_core(A, 128, 128, 8, 1, g_img + IMG_QKVD + (size_t)(18 + unit)*16384,
            sAh, sAl, sBh, sBl, acc);

    int lane = tid & 31, wid = tid >> 5;
    int g = lane >> 2, tig = lane & 3;
    int wr = wid & 1, wc = wid >> 1;
#pragma unroll
    for (int i = 0; i < 4; i++) {
        float s0 = 0.f, q0 = 0.f, s8 = 0.f, q8 = 0.f;
#pragma unroll
        for (int j = 0; j < 4; j++) {
            int lc = wc*32 + j*8 + tig*2;
            float b0 = sbias[lc], b1 = sbias[lc+1];
            acc[i][j][0] += b0; acc[i][j][1] += b1;
            acc[i][j][2] += b0; acc[i][j][3] += b1;
            s0 += acc[i][j][0] + acc[i][j][1];
            q0 += acc[i][j][0]*acc[i][j][0] + acc[i][j][1]*acc[i][j][1];
            s8 += acc[i][j][2] + acc[i][j][3];
            q8 += acc[i][j][2]*acc[i][j][2] + acc[i][j][3]*acc[i][j][3];
        }
#pragma unroll
        for (int off = 1; off <= 2; off <<= 1) {
            s0 += __shfl_xor_sync(0xffffffffu, s0, off);
            q0 += __shfl_xor_sync(0xffffffffu, q0, off);
            s8 += __shfl_xor_sync(0xffffffffu, s8, off);
            q8 += __shfl_xor_sync(0xffffffffu, q8, off);
        }
        if (tig == 0) {
            int r0 = wr*64 + i*16 + g;
            ssum[r0*4 + wc] = s0;      ssum2[r0*4 + wc] = q0;
            ssum[(r0+8)*4 + wc] = s8;  ssum2[(r0+8)*4 + wc] = q8;
        }
    }
    __syncthreads();
    if (tid < 128) {
        float s = ssum[tid*4] + ssum[tid*4+1] + ssum[tid*4+2] + ssum[tid*4+3];
        float q = ssum2[tid*4] + ssum2[tid*4+1] + ssum2[tid*4+2] + ssum2[tid*4+3];
        float mean = s * (1.0f/128.0f);
        float var  = q * (1.0f/128.0f) - mean*mean;
        smean[tid] = mean;
        srstd[tid] = rsqrtf(var + 1e-5f);
    }
    __syncthreads();
#pragma unroll
    for (int i = 0; i < 4; i++) {
        int rl = wr*64 + i*16 + g;
        float m0 = smean[rl],   rs0 = srstd[rl];
        float m8 = smean[rl+8], rs8 = srstd[rl+8];
#pragma unroll
        for (int j = 0; j < 4; j++) {
            int lc = wc*32 + j*8 + tig*2;
            float g0 = slg[lc], g1 = slg[lc+1], t0 = slb[lc], t1 = slb[lc+1];
            float o0 = 0.5f*((acc[i][j][0]-m0)*rs0*g0 + t0);
            float o1 = 0.5f*((acc[i][j][1]-m0)*rs0*g1 + t1);
            float o2 = 0.5f*((acc[i][j][2]-m8)*rs8*g0 + t0);
            float o3 = 0.5f*((acc[i][j][3]-m8)*rs8*g1 + t1);
            float* p0 = C + (size_t)(rowbase+rl)*128 + lc;
            float* p1 = C + (size_t)(rowbase+rl+8)*128 + lc;
            if (phase == 0) {
                *(float2*)p0 = make_float2(o0, o1);
                *(float2*)p1 = make_float2(o2, o3);
            } else {
                float2 v0 = *(float2*)p0, v1 = *(float2*)p1;
                *(float2*)p0 = make_float2(v0.x + o0, v0.y + o1);
                *(float2*)p1 = make_float2(v1.x + o2, v1.y + o3);
            }
        }
    }
}

// ---------------- V column sums ----------------
__global__ void vsum_kernel()
{
    int b = blockIdx.x, h = blockIdx.y, u = blockIdx.z, d = threadIdx.x;
    const float* V = g_scratch + OFF_QKV + (size_t)(u*3 + 2)*SZ + (size_t)b*SS*DD + h*DH + d;
    float s = 0.f;
#pragma unroll 8
    for (int k = 0; k < SS; k++) s += V[(size_t)k*DD];
    g_scratch[OFF_VSUM + (((size_t)u*64 + b)*2 + h)*64 + d] = s;
}

// ---------------- flash attention (proven R11): ctx = Vsum - softmax@V -------
#define ATTN_SMEM (4*64*68*4)

__global__ __launch_bounds__(256, 2)
void attn_flash()
{
    extern __shared__ float sm[];
    float* Qs = sm;
    float* Ks = sm + 64*68;      // transposed Ks[d][k]
    float* Vs = sm + 2*64*68;
    float* Ps = sm + 3*64*68;

    int tid = threadIdx.x;
    int u = blockIdx.z;
    int bh = blockIdx.y;
    int b = bh >> 1, h = bh & 1;
    int q0 = blockIdx.x * 64;

    const float* Qb = g_scratch + OFF_QKV + (size_t)(u*3 + 0)*SZ;
    const float* Kb = g_scratch + OFF_QKV + (size_t)(u*3 + 1)*SZ;
    const float* Vb = g_scratch + OFF_QKV + (size_t)(u*3 + 2)*SZ;
    size_t baseQ  = ((size_t)b*SS + q0)*DD + h*DH;
    size_t baseKV = ((size_t)b*SS)*DD + h*DH;

#pragma unroll
    for (int p = 0; p < 16; p++) {
        int idx = tid + p*256;
        int r = idx >> 6, c = idx & 63;
        Qs[r*68 + c] = Qb[baseQ + (size_t)r*DD + c];
    }

    int tx = tid & 15, ty = tid >> 4;
    float2 oacc[4][2];
    float m[4], l[4];
#pragma unroll
    for (int i = 0; i < 4; i++) {
        oacc[i][0] = make_float2(0.f, 0.f);
        oacc[i][1] = make_float2(0.f, 0.f);
        m[i] = -1e30f; l[i] = 0.f;
    }

    for (int kt = 0; kt < 8; kt++) {
        __syncthreads();
#pragma unroll
        for (int p = 0; p < 16; p++) {
            int idx = tid + p*256;
            int r = idx >> 6, c = idx & 63;
            size_t gidx = baseKV + (size_t)(kt*64 + r)*DD + c;
            Ks[c*68 + r] = Kb[gidx];
            Vs[r*68 + c] = Vb[gidx];
        }
        __syncthreads();

        float2 s2[4][2];
#pragma unroll
        for (int i = 0; i < 4; i++) { s2[i][0] = make_float2(0.f,0.f); s2[i][1] = make_float2(0.f,0.f); }
#pragma unroll 8
        for (int d = 0; d < 64; d++) {
            float4 k4 = *(const float4*)&Ks[d*68 + tx*4];
            float2 ka = make_float2(k4.x, k4.y);
            float2 kb2 = make_float2(k4.z, k4.w);
#pragma unroll
            for (int i = 0; i < 4; i++) {
                float2 qq = dup2(Qs[(ty*4 + i)*68 + d]);
                ffma2(s2[i][0], qq, ka);
                ffma2(s2[i][1], qq, kb2);
            }
        }

#pragma unroll
        for (int i = 0; i < 4; i++) {
            float s0 = s2[i][0].x * 0.125f;
            float s1 = s2[i][0].y * 0.125f;
            float s2v = s2[i][1].x * 0.125f;
            float s3 = s2[i][1].y * 0.125f;
            float tm = fmaxf(fmaxf(s0, s1), fmaxf(s2v, s3));
#pragma unroll
            for (int off = 8; off >= 1; off >>= 1)
                tm = fmaxf(tm, __shfl_xor_sync(0xffffffffu, tm, off));
            float mn = fmaxf(m[i], tm);
            float corr = __expf(m[i] - mn);
            float p0 = __expf(s0 - mn);
            float p1 = __expf(s1 - mn);
            float p2 = __expf(s2v - mn);
            float p3 = __expf(s3 - mn);
            float ps = p0 + p1 + p2 + p3;
#pragma unroll
            for (int off = 8; off >= 1; off >>= 1)
                ps += __shfl_xor_sync(0xffffffffu, ps, off);
            l[i] = l[i]*corr + ps;
            oacc[i][0].x *= corr; oacc[i][0].y *= corr;
            oacc[i][1].x *= corr; oacc[i][1].y *= corr;
            m[i] = mn;
            *(float4*)&Ps[(ty*4 + i)*68 + tx*4] = make_float4(p0, p1, p2, p3);
        }
        __syncthreads();

#pragma unroll 4
        for (int k4i = 0; k4i < 16; k4i++) {
            float4 p4[4];
#pragma unroll
            for (int i = 0; i < 4; i++)
                p4[i] = *(const float4*)&Ps[(ty*4 + i)*68 + k4i*4];
#pragma unroll
            for (int kk = 0; kk < 4; kk++) {
                float4 v4 = *(const float4*)&Vs[(k4i*4 + kk)*68 + tx*4];
                float2 va = make_float2(v4.x, v4.y);
                float2 vb2 = make_float2(v4.z, v4.w);
#pragma unroll
                for (int i = 0; i < 4; i++) {
                    float pk = (kk == 0) ? p4[i].x : (kk == 1) ? p4[i].y
                             : (kk == 2) ? p4[i].z : p4[i].w;
                    float2 pp = dup2(pk);
                    ffma2(oacc[i][0], pp, va);
                    ffma2(oacc[i][1], pp, vb2);
                }
            }
        }
    }

    float4 vs4 = *(const float4*)&g_scratch[OFF_VSUM + (((size_t)u*64 + b)*2 + h)*64 + tx*4];
    float* Cb = g_scratch + OFF_CTX + (size_t)u*SZ;
#pragma unroll
    for (int i = 0; i < 4; i++) {
        float inv = 1.f / l[i];
        size_t idx = ((size_t)b*SS + q0 + ty*4 + i)*DD + h*DH + tx*4;
        *(float4*)&Cb[idx] = make_float4(vs4.x - oacc[i][0].x*inv, vs4.y - oacc[i][0].y*inv,
                                         vs4.z - oacc[i][1].x*inv, vs4.w - oacc[i][1].y*inv);
    }
}

// ---------------- Whh transpose ----------------
__global__ void transpose_whh(const float* __restrict__ gWhh)
{
    int m = blockIdx.x;
    const float* src = gWhh + (size_t)m*384*128;
    float* dst = g_scratch + OFF_WHHT + (size_t)m*49152;
    for (int idx = threadIdx.x; idx < 128*384; idx += blockDim.x) {
        int k = idx / 384, n = idx % 384;
        dst[idx] = src[(size_t)n*128 + k];
    }
}

// ---------------- GRU recurrence ----------------
__global__ __launch_bounds__(384)
void gru_kernel(const float* __restrict__ gbhh)
{
    int dir6 = blockIdx.x >> 6;
    int b    = blockIdx.x & 63;
    int j    = threadIdx.x;

    const float* wp = g_scratch + OFF_WHHT + (size_t)dir6*49152 + j;
    float2 w2[64];
#pragma unroll
    for (int k = 0; k < 64; k++)
        w2[k] = make_float2(wp[(size_t)(2*k)*384], wp[(size_t)(2*k + 1)*384]);
    float bh = gbhh[dir6*384 + j];

    __shared__ float h[128];
    __shared__ float gh[384];
    __shared__ float gxs[384];
    __shared__ float hs[128];
    if (j < 128) { h[j] = 0.f; hs[j] = 0.f; }

    const float* gxb = g_scratch + OFF_GX + (size_t)dir6*GX_PER + (size_t)b*SS*384;
    int rev = dir6 & 1;
    const float2* h2 = (const float2*)h;

    for (int step = 0; step < SS; step++) {
        int t = rev ? (SS - 1 - step) : step;
        float gxv = gxb[(size_t)t*384 + j];
        __syncthreads();
        gxs[j] = gxv;
        float2 acc = make_float2(0.f, 0.f);
#pragma unroll
        for (int k = 0; k < 64; k++) ffma2(acc, w2[k], h2[k]);
        gh[j] = acc.x + acc.y + bh;
        __syncthreads();
        if (j < 128) {
            float r  = 1.f / (1.f + __expf(-(gxs[j]       + gh[j])));
            float z  = 1.f / (1.f + __expf(-(gxs[128 + j] + gh[128 + j])));
            float n  = tanhf(gxs[256 + j] + r * gh[256 + j]);
            float hn = (1.f - z)*n + z*h[j];
            h[j]  = hn;
            hs[j] += hn;
        }
    }
    __syncthreads();
    if (j < 128) g_scratch[OFF_HSUM + ((size_t)dir6*64 + b)*128 + j] = hs[j];
}

// ---------------- combine + head ----------------
__global__ void combine_kernel()
{
    int b = blockIdx.x, j = threadIdx.x;
    int seg = j >> 7, i = j & 127;
    float v = g_scratch[OFF_HSUM + ((size_t)seg*64 + b)*128 + i]
            + g_scratch[OFF_HSUM + ((size_t)(seg + 3)*64 + b)*128 + i];
    g_scratch[OFF_OM + (size_t)b*384 + j] = v * (0.5f / 512.0f);
}

__global__ __launch_bounds__(256)
void head_kernel(const float* __restrict__ fW1, const float* __restrict__ fb1,
                 const float* __restrict__ bng, const float* __restrict__ bnb,
                 const float* __restrict__ fW2, const float* __restrict__ fb2,
                 float* __restrict__ out)
{
    __shared__ float oms[384];
    __shared__ float hsh[256];
    int b = blockIdx.x, tid = threadIdx.x;
    for (int k = tid; k < 384; k += 256) oms[k] = g_scratch[OFF_OM + (size_t)b*384 + k];
    __syncthreads();
    float acc = fb1[tid];
    for (int k = 0; k < 384; k++) acc += oms[k] * fW1[(size_t)k*256 + tid];
    float hv = acc * rsqrtf(1.0f + 1e-5f) * bng[tid] + bnb[tid];
    hv = fminf(fmaxf(hv, 0.f), 6.f);
    hsh[tid] = hv;
    __syncthreads();
    if (tid < 8) {
        float a2 = fb2[tid];
        for (int k = 0; k < 256; k++) a2 += hsh[k] * fW2[k*8 + tid];
        out[b*8 + tid] = a2;
    }
}

// ---------------- host launcher ----------------
extern "C" void kernel_launch(void* const* d_in, const int* in_sizes, int n_in,
                              void* d_out, int out_size)
{
    (void)in_sizes; (void)n_in; (void)out_size;
    const float* text   = (const float*)d_in[0];
    const float* visual = (const float*)d_in[1];
    const float* audio  = (const float*)d_in[2];
    const float* fc1W = (const float*)d_in[3];
    const float* fc1b = (const float*)d_in[4];
    const float* fc2W = (const float*)d_in[5];
    const float* fc2b = (const float*)d_in[6];
    const float* fc3W = (const float*)d_in[7];
    const float* fc3b = (const float*)d_in[8];
    const float* Wq = (const float*)d_in[9];
    const float* bq = (const float*)d_in[10];
    const float* Wk = (const float*)d_in[11];
    const float* bk = (const float*)d_in[12];
    const float* Wv = (const float*)d_in[13];
    const float* bv = (const float*)d_in[14];
    const float* Wd = (const float*)d_in[15];
    const float* bd = (const float*)d_in[16];
    const float* lng = (const float*)d_in[17];
    const float* lnb = (const float*)d_in[18];
    const float* gWih = (const float*)d_in[19];
    const float* gWhh = (const float*)d_in[20];
    const float* gbih = (const float*)d_in[21];
    const float* gbhh = (const float*)d_in[22];
    const float* fW1 = (const float*)d_in[23];
    const float* fb1 = (const float*)d_in[24];
    const float* bng = (const float*)d_in[25];
    const float* bnb = (const float*)d_in[26];
    const float* fW2 = (const float*)d_in[27];
    const float* fb2 = (const float*)d_in[28];
    float* out = (float*)d_out;

    cudaFuncSetAttribute(attn_flash, cudaFuncAttributeMaxDynamicSharedMemorySize, ATTN_SMEM);

    // prepack weight images + Whh transpose (independent of data path)
    prepack_sq<<<24, 128>>>(Wq, Wk, Wv, Wd);
    prepack_wih<<<18, 128>>>(gWih);
    prepack_proj<<<27, 128>>>(fc1W, fc2W, fc3W);
    transpose_whh<<<6, 256>>>(gWhh);

    // input projections (HMMA)
    mm_proj<<<dim3(RTOT/128, 1, 3), 256>>>(text, visual, audio, fc1b, fc2b, fc3b);

    // 18 QKV projections (HMMA, one launch)
    mm_qkv<<<dim3(RTOT/128, 1, 18), 256>>>(bq, bk, bv);

    // attention
    vsum_kernel<<<dim3(64, 2, 6), 64>>>();
    attn_flash<<<dim3(8, 128, 6), 256, ATTN_SMEM>>>();

    // out-proj + LN + average (HMMA)
    mm_ln<<<dim3(RTOT/128, 1, 3), 256>>>(bd, lng, lnb, 0);
    mm_ln<<<dim3(RTOT/128, 1, 3), 256>>>(bd, lng, lnb, 1);

    // GRU input gates (HMMA, one launch)
    mm_gx<<<dim3(RTOT/128, 3, 6), 256>>>(gbih);

    // recurrence, pooling, head
    gru_kernel<<<384, 384>>>(gbhh);
    combine_kernel<<<64, 384>>>();
    head_kernel<<<64, 256>>>(fW1, fb1, bng, bnb, fW2, fb2, out);
}